// round 6
// baseline (speedup 1.0000x reference)
#include <cuda_runtime.h>

// gabor_fixedResponse, round 6: fused one-CTA-per-filter kernel.
//   vs round 5: (a) plain float4 stores instead of __stcs (L2 write-back
//   absorbs the 134MB instead of streaming at DRAM rate), (b) bit-reversed
//   filter<->block mapping so every wave mixes DFT-heavy (low f) and
//   store-heavy (high f) CTAs -> fma and LSU/LTS pipes overlap.

#define NFILT  512
#define NBINS  8
#define NPAIR  2
#define WHALF  3

typedef unsigned long long ull;

__device__ __forceinline__ ull pk2(float lo, float hi) {
    ull r; asm("mov.b64 %0, {%1,%2};" : "=l"(r) : "f"(lo), "f"(hi)); return r;
}
__device__ __forceinline__ void upk2(ull v, float& lo, float& hi) {
    asm("mov.b64 {%0,%1}, %2;" : "=f"(lo), "=f"(hi) : "l"(v));
}
__device__ __forceinline__ ull fma2(ull a, ull b, ull c) {
    ull d; asm("fma.rn.f32x2 %0, %1, %2, %3;" : "=l"(d) : "l"(a), "l"(b), "l"(c)); return d;
}
__device__ __forceinline__ ull mul2(ull a, ull b) {
    ull d; asm("mul.rn.f32x2 %0, %1, %2;" : "=l"(d) : "l"(a), "l"(b)); return d;
}

// exact double of 2*pi/16000 as the reference computes it; fp32 image defect
constexpr double W0D  = 6.283185307179586 / 16000.0;
constexpr float  C32F = (float)W0D;
constexpr float  DCFF = (float)((double)C32F - W0D);
#define PI1024 3.0679615757712823e-3f   /* pi/1024 */

__global__ __launch_bounds__(512, 2)
void fused_kernel(const float* __restrict__ Q, const float* __restrict__ fc,
                  float* __restrict__ out) {
    // bit-reverse 9-bit block id -> filter id: mixes envelope lengths per wave
    int f    = (int)(__brev((unsigned)blockIdx.x) >> 23);
    int tid  = threadIdx.x;
    int lane = tid & 31;
    int w    = tid >> 5;          // warp 0..15
    int bg   = w & 1;             // batch group (32 batches each)
    int bh   = (w >> 1) & 1;      // bin half (4 bins each)
    int seg  = w >> 2;            // segment 0..3, 128 samples each
    int b    = bg * 32 + lane;

    __shared__ float s_carr[1024];
    __shared__ float s_ar[4][2][64][5];   // [seg][bh][b][bin(4)+pad]
    __shared__ float s_ai[4][2][64][5];
    __shared__ float s_max[2];

    float fcv = __ldg(&fc[f]);
    float wph = C32F * fcv;                        // fl(fl(2pi/16000)*fc)
    float e1  = fmaf(C32F, fcv, -wph);             // exact product residue
    float dwf = fmaf(fcv, DCFF, -e1);              // fl(w) - pi*(2f+1)/1024
    int stepm = 2 * f + 1;

    // carrier row: 2 entries/thread; exact int phase + tiny fp32 delta
    {
        float2 cv;
        int t0 = tid << 1;
#pragma unroll
        for (int e = 0; e < 2; e++) {
            int n = t0 + e + 1;
            int m = (stepm * n) & 2047;            // phase/(pi/1024) mod 2048
            float nf  = (float)n;
            float p   = wph * nf;
            float eta = fmaf(wph, nf, -p);         // rounding residue of fl(w*n)
            float del = fmaf(dwf, nf, eta);
            ((float*)&cv)[e] = __cosf(fmaf(PI1024, (float)m, del));
        }
        *(float2*)(s_carr + t0) = cv;
    }

    // ---------------- Phase 1: windowed DFT max ----------------
    float qv    = Q[b * NFILT + f];
    float bw    = fcv / qv;
    float alpha = bw * 1.2533141373155003f;        // 0.5*sqrt(2*pi)
    float bq    = alpha / 16000.0f;
    float t2    = bq * bq;

    int klo = ((2 * f + 3) >> 2) - WHALF;          // window [kround-3, kround+4]
    if (klo < 0) klo = 0;
    if (klo > 256 - (NBINS - 1)) klo = 256 - (NBINS - 1);
    int kb = klo + 4 * bh;                         // this thread's 4 bins

    ull uc2[NPAIR], us2[NPAIR], ucq[NPAIR], usq[NPAIR], nusq[NPAIR];
#pragma unroll
    for (int p = 0; p < NPAIR; p++) {
        float c0, s0, c1, s1, cq0, sq0, cq1, sq1;
        float th0 = (float)(kb + 2 * p)     * (3.14159265358979f / 256.0f);
        float th1 = (float)(kb + 2 * p + 1) * (3.14159265358979f / 256.0f);
        __sincosf(th0, &s0, &c0);  __sincosf(th1, &s1, &c1);
        __sincosf(2.0f * th0, &sq0, &cq0);  __sincosf(2.0f * th1, &sq1, &cq1);
        uc2[p] = pk2(c0, c1);   us2[p] = pk2(s0, s1);
        ucq[p] = pk2(cq0, cq1); usq[p] = pk2(sq0, sq1); nusq[p] = pk2(-sq0, -sq1);
    }
    ull ar2[NPAIR], ai2[NPAIR];
#pragma unroll
    for (int p = 0; p < NPAIR; p++) { ar2[p] = 0ull; ai2[p] = 0ull; }

    // envelope recurrence seeds, n = n0 .. n0+127
    int   n0 = seg * 128 + 1;
    float x0 = bq * (float)n0;
    float g  = __expf(-x0 * x0);
    float r  = __expf(-t2 * (float)(2 * n0 + 1));
    float qq = __expf(-2.0f * t2);

    __syncthreads();

    // acc <- acc*u^2 + (y0*u + y1); 4 samples/iter; warp-uniform early exit
    const float4* cp4 = (const float4*)(s_carr + seg * 128);
#pragma unroll 2
    for (int j = 0; j < 32; j++) {
        if (!__ballot_sync(0xffffffffu, g > 1e-10f)) break;
        float4 c = cp4[j];
        float y0 = g * c.x; g *= r; r *= qq;
        float y1 = g * c.y; g *= r; r *= qq;
        ull yy0 = pk2(y0, y0), yy1 = pk2(y1, y1);
#pragma unroll
        for (int p = 0; p < NPAIR; p++) {
            ull s1v = mul2(yy0, us2[p]);               // zi = y0*us
            ull s2v = fma2(ar2[p], usq[p], s1v);
            ull ain = fma2(ai2[p], ucq[p], s2v);       // ai' = ai*uc2 + ar*us2 + zi
            ull s3v = fma2(yy0, uc2[p], yy1);          // zr = y0*uc + y1
            ull s4v = fma2(ai2[p], nusq[p], s3v);
            ar2[p]  = fma2(ar2[p], ucq[p], s4v);       // ar' = ar*uc2 - ai*us2 + zr
            ai2[p]  = ain;
        }
        y0 = g * c.z; g *= r; r *= qq;
        y1 = g * c.w; g *= r; r *= qq;
        yy0 = pk2(y0, y0); yy1 = pk2(y1, y1);
#pragma unroll
        for (int p = 0; p < NPAIR; p++) {
            ull s1v = mul2(yy0, us2[p]);
            ull s2v = fma2(ar2[p], usq[p], s1v);
            ull ain = fma2(ai2[p], ucq[p], s2v);
            ull s3v = fma2(yy0, uc2[p], yy1);
            ull s4v = fma2(ai2[p], nusq[p], s3v);
            ar2[p]  = fma2(ar2[p], ucq[p], s4v);
            ai2[p]  = ain;
        }
    }

#pragma unroll
    for (int p = 0; p < NPAIR; p++) {
        upk2(ar2[p], s_ar[seg][bh][b][2 * p], s_ar[seg][bh][b][2 * p + 1]);
        upk2(ai2[p], s_ai[seg][bh][b][2 * p], s_ai[seg][bh][b][2 * p + 1]);
    }
    __syncthreads();

    // combine: X_k = sum_s acc_s * (i^k)^(3-s)  (u^128 = i^k exactly)
    if (tid < 64) {
        int bb = tid;
        float msq = 0.0f;
#pragma unroll
        for (int i = 0; i < NBINS; i++) {
            int k = klo + i;
            int h = i >> 2, ii = i & 3;
            float R = 0.0f, I = 0.0f;
#pragma unroll
            for (int s = 0; s < 4; s++) {
                float rr = s_ar[s][h][bb][ii];
                float iv = s_ai[s][h][bb][ii];
                int mc = (k * (3 - s)) & 3;
                float r2 = (mc == 0) ? rr : (mc == 1) ? -iv : (mc == 2) ? -rr : iv;
                float i2 = (mc == 0) ? iv : (mc == 1) ?  rr : (mc == 2) ? -iv : -rr;
                R += r2; I += i2;
            }
            msq = fmaxf(msq, fmaf(R, R, I * I));
        }
#pragma unroll
        for (int o = 16; o; o >>= 1)
            msq = fmaxf(msq, __shfl_xor_sync(0xffffffffu, msq, o));
        if (lane == 0) s_max[tid >> 5] = msq;
    }
    __syncthreads();

    float inv = rsqrtf(fmaxf(s_max[0], s_max[1]));

    // ---------------- Phase 2: normalized, flipped output ----------------
    // Thread = (batch b2, t-lane ch): elements t = 32v + 4ch + e, v = 0..31.
    // 4 stride-32 envelope chains, ascending n (ratios <= 1, underflow ok).
    int b2 = tid >> 3;                   // 0..63
    int ch = tid & 7;                    // 0..7

    float qv2 = Q[b2 * NFILT + f];
    float bq2 = (fcv / qv2 * 1.2533141373155003f) / 16000.0f;
    float s2t = bq2 * bq2;

    int N0 = 32 - 4 * ch;                // n at v=31, e=0  (>= 4)
    float ge[4], re[4];
#pragma unroll
    for (int e = 0; e < 4; e++) {
        float x = bq2 * (float)(N0 - e);
        ge[e] = __expf(-x * x) * inv;
    }
    float rbase = __expf(-s2t * (float)(64 * N0 + 1024));  // env(n+32)/env(n) @ N0
    float s1    = __expf(64.0f * s2t);
    float qq32  = __expf(-2048.0f * s2t);
    re[0] = rbase;
    re[1] = rbase * s1;
    float s1sq = s1 * s1;
    re[2] = rbase * s1sq;
    re[3] = rbase * (s1sq * s1);

    float* op = out + ((size_t)(b2 * NFILT + f) << 10);
#pragma unroll 4
    for (int v = 31; v >= 0; v--) {
        int N = 1024 - 32 * v - 4 * ch;                    // n at e=0
        float4 c = *(const float4*)(s_carr + (N - 4));     // n = N-3 .. N
        float4 o;
        o.x = ge[0] * c.w;   // t = 32v+4ch+0 <-> n = N
        o.y = ge[1] * c.z;
        o.z = ge[2] * c.y;
        o.w = ge[3] * c.x;   // t = +3 <-> n = N-3
        *(float4*)(op + 32 * v + 4 * ch) = o;              // plain store: L2 absorbs
#pragma unroll
        for (int e = 0; e < 4; e++) { ge[e] *= re[e]; re[e] *= qq32; }
    }
}

extern "C" void kernel_launch(void* const* d_in, const int* in_sizes, int n_in,
                              void* d_out, int out_size) {
    const float* Q  = (const float*)d_in[0];
    const float* fc = (const float*)d_in[1];
    float* out = (float*)d_out;
    (void)in_sizes; (void)n_in; (void)out_size;

    fused_kernel<<<NFILT, 512>>>(Q, fc, out);   // 512 CTAs, bit-reversed f map
}

// round 7
// speedup vs baseline: 1.1587x; 1.1587x over previous
#include <cuda_runtime.h>

// gabor_fixedResponse, round 7: fused one-CTA-per-filter kernel.
//   Phase 1 (unchanged from round 5): carrier row in smem (exact int phase
//     reduction + fp32 residue), 8-bin packed-f32x2 Horner DFT, 4 seg x 2
//     bin-halves x 64 batches, envelope-death ballot early exit.
//   NEW Pass A: env underflows to exact 0 for bq*n > 9.6 -> those outputs are
//     0 regardless of normalization. Warp-uniform 128-elem blocks; dead blocks
//     stream zero STG.128 BEFORE the reduction barrier (overlaps heavy DFT).
//   NEW Pass B: live blocks only; per-element direct __expf (matches reference
//     fl(bq*n) rounding exactly), carrier*inv pre-folded in smem.

#define NFILT  512
#define NBINS  8
#define NPAIR  2
#define WHALF  3
#define DEADX  9.6f   /* bq*n beyond this: env < 1e-40 -> output exact 0 */

typedef unsigned long long ull;

__device__ __forceinline__ ull pk2(float lo, float hi) {
    ull r; asm("mov.b64 %0, {%1,%2};" : "=l"(r) : "f"(lo), "f"(hi)); return r;
}
__device__ __forceinline__ void upk2(ull v, float& lo, float& hi) {
    asm("mov.b64 {%0,%1}, %2;" : "=f"(lo), "=f"(hi) : "l"(v));
}
__device__ __forceinline__ ull fma2(ull a, ull b, ull c) {
    ull d; asm("fma.rn.f32x2 %0, %1, %2, %3;" : "=l"(d) : "l"(a), "l"(b), "l"(c)); return d;
}
__device__ __forceinline__ ull mul2(ull a, ull b) {
    ull d; asm("mul.rn.f32x2 %0, %1, %2;" : "=l"(d) : "l"(a), "l"(b)); return d;
}

// exact double of 2*pi/16000 as the reference computes it; fp32 image defect
constexpr double W0D  = 6.283185307179586 / 16000.0;
constexpr float  C32F = (float)W0D;
constexpr float  DCFF = (float)((double)C32F - W0D);
#define PI1024 3.0679615757712823e-3f   /* pi/1024 */

__global__ __launch_bounds__(512, 2)
void fused_kernel(const float* __restrict__ Q, const float* __restrict__ fc,
                  float* __restrict__ out) {
    int f    = blockIdx.x;
    int tid  = threadIdx.x;
    int lane = tid & 31;
    int w    = tid >> 5;          // warp 0..15
    int bg   = w & 1;             // batch group (32 batches each)
    int bh   = (w >> 1) & 1;      // bin half (4 bins each)
    int seg  = w >> 2;            // segment 0..3, 128 samples each
    int b    = bg * 32 + lane;

    __shared__ float s_carr[1024];
    __shared__ float s_cinv[1024];
    __shared__ float s_bq[64];
    __shared__ float s_ar[4][2][64][5];   // [seg][bh][b][bin(4)+pad]
    __shared__ float s_ai[4][2][64][5];
    __shared__ float s_max[2];

    float fcv = __ldg(&fc[f]);
    float wph = C32F * fcv;                        // fl(fl(2pi/16000)*fc)
    float e1  = fmaf(C32F, fcv, -wph);             // exact product residue
    float dwf = fmaf(fcv, DCFF, -e1);              // fl(w) - pi*(2f+1)/1024
    int stepm = 2 * f + 1;

    // carrier row: 2 entries/thread; exact int phase + tiny fp32 delta
    {
        float2 cv;
        int t0 = tid << 1;
#pragma unroll
        for (int e = 0; e < 2; e++) {
            int n = t0 + e + 1;
            int m = (stepm * n) & 2047;            // phase/(pi/1024) mod 2048
            float nf  = (float)n;
            float p   = wph * nf;
            float eta = fmaf(wph, nf, -p);         // rounding residue of fl(w*n)
            float del = fmaf(dwf, nf, eta);
            ((float*)&cv)[e] = __cosf(fmaf(PI1024, (float)m, del));
        }
        *(float2*)(s_carr + t0) = cv;
    }

    // ---------------- Phase 1: windowed DFT max ----------------
    float qv    = Q[b * NFILT + f];
    float bw    = fcv / qv;
    float alpha = bw * 1.2533141373155003f;        // 0.5*sqrt(2*pi)
    float bq    = alpha / 16000.0f;
    float t2    = bq * bq;
    if (w < 2) s_bq[b] = bq;                       // w0: b=0..31, w1: b=32..63

    int klo = ((2 * f + 3) >> 2) - WHALF;          // window [kround-3, kround+4]
    if (klo < 0) klo = 0;
    if (klo > 256 - (NBINS - 1)) klo = 256 - (NBINS - 1);
    int kb = klo + 4 * bh;                         // this thread's 4 bins

    ull uc2[NPAIR], us2[NPAIR], ucq[NPAIR], usq[NPAIR], nusq[NPAIR];
#pragma unroll
    for (int p = 0; p < NPAIR; p++) {
        float c0, s0, c1, s1, cq0, sq0, cq1, sq1;
        float th0 = (float)(kb + 2 * p)     * (3.14159265358979f / 256.0f);
        float th1 = (float)(kb + 2 * p + 1) * (3.14159265358979f / 256.0f);
        __sincosf(th0, &s0, &c0);  __sincosf(th1, &s1, &c1);
        __sincosf(2.0f * th0, &sq0, &cq0);  __sincosf(2.0f * th1, &sq1, &cq1);
        uc2[p] = pk2(c0, c1);   us2[p] = pk2(s0, s1);
        ucq[p] = pk2(cq0, cq1); usq[p] = pk2(sq0, sq1); nusq[p] = pk2(-sq0, -sq1);
    }
    ull ar2[NPAIR], ai2[NPAIR];
#pragma unroll
    for (int p = 0; p < NPAIR; p++) { ar2[p] = 0ull; ai2[p] = 0ull; }

    // envelope recurrence seeds, n = n0 .. n0+127
    int   n0 = seg * 128 + 1;
    float x0 = bq * (float)n0;
    float g  = __expf(-x0 * x0);
    float r  = __expf(-t2 * (float)(2 * n0 + 1));
    float qq = __expf(-2.0f * t2);

    __syncthreads();                               // carrier + s_bq ready

    // acc <- acc*u^2 + (y0*u + y1); 4 samples/iter; warp-uniform early exit
    const float4* cp4 = (const float4*)(s_carr + seg * 128);
#pragma unroll 2
    for (int j = 0; j < 32; j++) {
        if (!__ballot_sync(0xffffffffu, g > 1e-10f)) break;
        float4 c = cp4[j];
        float y0 = g * c.x; g *= r; r *= qq;
        float y1 = g * c.y; g *= r; r *= qq;
        ull yy0 = pk2(y0, y0), yy1 = pk2(y1, y1);
#pragma unroll
        for (int p = 0; p < NPAIR; p++) {
            ull s1v = mul2(yy0, us2[p]);               // zi = y0*us
            ull s2v = fma2(ar2[p], usq[p], s1v);
            ull ain = fma2(ai2[p], ucq[p], s2v);       // ai' = ai*uc2 + ar*us2 + zi
            ull s3v = fma2(yy0, uc2[p], yy1);          // zr = y0*uc + y1
            ull s4v = fma2(ai2[p], nusq[p], s3v);
            ar2[p]  = fma2(ar2[p], ucq[p], s4v);       // ar' = ar*uc2 - ai*us2 + zr
            ai2[p]  = ain;
        }
        y0 = g * c.z; g *= r; r *= qq;
        y1 = g * c.w; g *= r; r *= qq;
        yy0 = pk2(y0, y0); yy1 = pk2(y1, y1);
#pragma unroll
        for (int p = 0; p < NPAIR; p++) {
            ull s1v = mul2(yy0, us2[p]);
            ull s2v = fma2(ar2[p], usq[p], s1v);
            ull ain = fma2(ai2[p], ucq[p], s2v);
            ull s3v = fma2(yy0, uc2[p], yy1);
            ull s4v = fma2(ai2[p], nusq[p], s3v);
            ar2[p]  = fma2(ar2[p], ucq[p], s4v);
            ai2[p]  = ain;
        }
    }

#pragma unroll
    for (int p = 0; p < NPAIR; p++) {
        upk2(ar2[p], s_ar[seg][bh][b][2 * p], s_ar[seg][bh][b][2 * p + 1]);
        upk2(ai2[p], s_ai[seg][bh][b][2 * p], s_ai[seg][bh][b][2 * p + 1]);
    }

    // ---------------- Pass A: dead-block zero stores (pre-reduction) -----
    // Warp-task tk = (warp, j): row r = tk>>1, half h = tk&1 (512 elems).
    // Block v = 128 elems; dead iff bq * n_min_block > DEADX (warp-uniform).
    // Zero outputs don't need inv -> stream them while heavy warps still DFT.
    const float4 z4 = make_float4(0.f, 0.f, 0.f, 0.f);
#pragma unroll
    for (int j = 0; j < 8; j++) {
        int tk = (w << 3) | j;
        int rr = tk >> 1, h = tk & 1;
        float bqr = s_bq[rr];
        float* base = out + ((size_t)(rr * NFILT + f) << 10) + (h << 9);
#pragma unroll
        for (int v = 0; v < 4; v++) {
            float nmin = (float)(897 - (h << 9) - (v << 7));
            if (bqr * nmin > DEADX)
                __stcs((float4*)(base + (v << 7) + (lane << 2)), z4);
        }
    }
    __syncthreads();                               // s_ar/ai + pass A done

    // combine: X_k = sum_s acc_s * (i^k)^(3-s)  (u^128 = i^k exactly)
    if (tid < 64) {
        int bb = tid;
        float msq = 0.0f;
#pragma unroll
        for (int i = 0; i < NBINS; i++) {
            int k = klo + i;
            int h = i >> 2, ii = i & 3;
            float R = 0.0f, I = 0.0f;
#pragma unroll
            for (int s = 0; s < 4; s++) {
                float rr = s_ar[s][h][bb][ii];
                float iv = s_ai[s][h][bb][ii];
                int mc = (k * (3 - s)) & 3;
                float r2 = (mc == 0) ? rr : (mc == 1) ? -iv : (mc == 2) ? -rr : iv;
                float i2 = (mc == 0) ? iv : (mc == 1) ?  rr : (mc == 2) ? -iv : -rr;
                R += r2; I += i2;
            }
            msq = fmaxf(msq, fmaf(R, R, I * I));
        }
#pragma unroll
        for (int o = 16; o; o >>= 1)
            msq = fmaxf(msq, __shfl_xor_sync(0xffffffffu, msq, o));
        if (lane == 0) s_max[tid >> 5] = msq;
    }
    __syncthreads();

    float inv = rsqrtf(fmaxf(s_max[0], s_max[1]));

    // fold inv into carrier: s_cinv[n-1] = cos * inv
    {
        int t0 = tid << 1;
        float2 cv = *(float2*)(s_carr + t0);
        cv.x *= inv; cv.y *= inv;
        *(float2*)(s_cinv + t0) = cv;
    }
    __syncthreads();

    // ---------------- Pass B: live-block stores ----------------
    // Lane elements: t = 512h + 128v + 4*lane + e  <->  n = nb - 4*lane - e,
    // nb = 1024 - 512h - 128v. Direct per-element env = __expf(-(bq*n)^2)
    // with fl(bq*n) matching the reference's rounding exactly.
#pragma unroll
    for (int j = 0; j < 8; j++) {
        int tk = (w << 3) | j;
        int rr = tk >> 1, h = tk & 1;
        float bqr = s_bq[rr];
        float* base = out + ((size_t)(rr * NFILT + f) << 10) + (h << 9);
#pragma unroll
        for (int v = 0; v < 4; v++) {
            float nmin = (float)(897 - (h << 9) - (v << 7));
            if (bqr * nmin <= DEADX) {
                int nb = 1024 - (h << 9) - (v << 7);
                int nl = nb - (lane << 2);                 // n at e=0
                float4 c = *(const float4*)(s_cinv + (nl - 4));  // n-3..n
                float nf = (float)nl;
                float x0v = bqr * nf;
                float x1v = bqr * (nf - 1.0f);
                float x2v = bqr * (nf - 2.0f);
                float x3v = bqr * (nf - 3.0f);
                float4 o;
                o.x = __expf(-x0v * x0v) * c.w;   // e=0 <-> n = nl
                o.y = __expf(-x1v * x1v) * c.z;
                o.z = __expf(-x2v * x2v) * c.y;
                o.w = __expf(-x3v * x3v) * c.x;   // e=3 <-> n = nl-3
                __stcs((float4*)(base + (v << 7) + (lane << 2)), o);
            }
        }
    }
}

extern "C" void kernel_launch(void* const* d_in, const int* in_sizes, int n_in,
                              void* d_out, int out_size) {
    const float* Q  = (const float*)d_in[0];
    const float* fc = (const float*)d_in[1];
    float* out = (float*)d_out;
    (void)in_sizes; (void)n_in; (void)out_size;

    fused_kernel<<<NFILT, 512>>>(Q, fc, out);   // 512 CTAs, one per filter
}

// round 8
// speedup vs baseline: 1.2943x; 1.1170x over previous
#include <cuda_runtime.h>

// gabor_fixedResponse, round 8: fused one-CTA-per-filter kernel.
//   f < 64  (fc < 1kHz): full 64-batch packed-f32x2 Horner DFT (round-7 path).
//   f >= 64: |X|max(b) is provably monotone in Q (best-bin offset is 0.25 bins
//     for every f; bq >= 7.8e-3 > stationary point 2.2e-3; no truncation/image)
//     -> evaluate only the top-2-Q batches with a direct-sum micro-DFT
//     (2 batches x 8 bins x 32 interleaved chains, exact int phase seeding).
//   Pass A: env==0 blocks (bq*n > 9.6) stream zeros before any reduction.
//   Pass B: live blocks, per-element __expf, carrier*inv folded in smem.

#define NFILT  512
#define NBINS  8
#define NPAIR  2
#define WHALF  3
#define DEADX  9.6f   /* bq*n beyond this: env underflows -> output exact 0 */
#define FSPLIT 64     /* f below this: full 64-batch DFT */

typedef unsigned long long ull;

__device__ __forceinline__ ull pk2(float lo, float hi) {
    ull r; asm("mov.b64 %0, {%1,%2};" : "=l"(r) : "f"(lo), "f"(hi)); return r;
}
__device__ __forceinline__ void upk2(ull v, float& lo, float& hi) {
    asm("mov.b64 {%0,%1}, %2;" : "=f"(lo), "=f"(hi) : "l"(v));
}
__device__ __forceinline__ ull fma2(ull a, ull b, ull c) {
    ull d; asm("fma.rn.f32x2 %0, %1, %2, %3;" : "=l"(d) : "l"(a), "l"(b), "l"(c)); return d;
}
__device__ __forceinline__ ull mul2(ull a, ull b) {
    ull d; asm("mul.rn.f32x2 %0, %1, %2;" : "=l"(d) : "l"(a), "l"(b)); return d;
}

constexpr double W0D  = 6.283185307179586 / 16000.0;
constexpr float  C32F = (float)W0D;
constexpr float  DCFF = (float)((double)C32F - W0D);
#define PI1024 3.0679615757712823e-3f   /* pi/1024 */
#define PI256  1.2271846303085129e-2f   /* pi/256  */

__global__ __launch_bounds__(512, 2)
void fused_kernel(const float* __restrict__ Q, const float* __restrict__ fc,
                  float* __restrict__ out) {
    int f    = blockIdx.x;
    int tid  = threadIdx.x;
    int lane = tid & 31;
    int w    = tid >> 5;          // warp 0..15

    __shared__ float s_carr[1024];
    __shared__ float s_cinv[1024];
    __shared__ float s_bq[64];
    __shared__ float s_ar[4][2][64][5];   // heavy path only
    __shared__ float s_ai[4][2][64][5];
    __shared__ float s_max[2];
    __shared__ float s_part[16];
    __shared__ int   s_top[2];

    float fcv = __ldg(&fc[f]);
    float wph = C32F * fcv;                        // fl(fl(2pi/16000)*fc)
    float e1  = fmaf(C32F, fcv, -wph);
    float dwf = fmaf(fcv, DCFF, -e1);              // fl(w) - pi*(2f+1)/1024
    int stepm = 2 * f + 1;

    // carrier row: 2 entries/thread; exact int phase + tiny fp32 delta
    {
        float2 cv;
        int t0 = tid << 1;
#pragma unroll
        for (int e = 0; e < 2; e++) {
            int n = t0 + e + 1;
            int m = (stepm * n) & 2047;
            float nf  = (float)n;
            float p   = wph * nf;
            float eta = fmaf(wph, nf, -p);
            float del = fmaf(dwf, nf, eta);
            ((float*)&cv)[e] = __cosf(fmaf(PI1024, (float)m, del));
        }
        *(float2*)(s_carr + t0) = cv;
    }
    // per-row bq for pass A/B
    if (tid < 64) {
        float qv = Q[tid * NFILT + f];
        s_bq[tid] = (fcv / qv) * 1.2533141373155003f / 16000.0f;
    }

    int klo = ((2 * f + 3) >> 2) - WHALF;
    if (klo < 0) klo = 0;
    if (klo > 256 - (NBINS - 1)) klo = 256 - (NBINS - 1);

    __syncthreads();                               // carrier + s_bq ready

    const float4 z4 = make_float4(0.f, 0.f, 0.f, 0.f);

    if (f < FSPLIT) {
        // ============== HEAVY PATH: full 64-batch Horner DFT ==============
        int bg  = w & 1, bh = (w >> 1) & 1, seg = w >> 2;
        int b   = bg * 32 + lane;
        float qv    = Q[b * NFILT + f];
        float bq    = (fcv / qv) * 1.2533141373155003f / 16000.0f;
        float t2    = bq * bq;
        int kb = klo + 4 * bh;

        ull uc2[NPAIR], us2[NPAIR], ucq[NPAIR], usq[NPAIR], nusq[NPAIR];
#pragma unroll
        for (int p = 0; p < NPAIR; p++) {
            float c0, s0, c1, s1, cq0, sq0, cq1, sq1;
            float th0 = (float)(kb + 2 * p)     * (3.14159265358979f / 256.0f);
            float th1 = (float)(kb + 2 * p + 1) * (3.14159265358979f / 256.0f);
            __sincosf(th0, &s0, &c0);  __sincosf(th1, &s1, &c1);
            __sincosf(2.0f * th0, &sq0, &cq0);  __sincosf(2.0f * th1, &sq1, &cq1);
            uc2[p] = pk2(c0, c1);   us2[p] = pk2(s0, s1);
            ucq[p] = pk2(cq0, cq1); usq[p] = pk2(sq0, sq1); nusq[p] = pk2(-sq0, -sq1);
        }
        ull ar2[NPAIR], ai2[NPAIR];
#pragma unroll
        for (int p = 0; p < NPAIR; p++) { ar2[p] = 0ull; ai2[p] = 0ull; }

        int   n0 = seg * 128 + 1;
        float x0 = bq * (float)n0;
        float g  = __expf(-x0 * x0);
        float r  = __expf(-t2 * (float)(2 * n0 + 1));
        float qq = __expf(-2.0f * t2);

        const float4* cp4 = (const float4*)(s_carr + seg * 128);
#pragma unroll 2
        for (int j = 0; j < 32; j++) {
            if (!__ballot_sync(0xffffffffu, g > 1e-10f)) break;
            float4 c = cp4[j];
            float y0 = g * c.x; g *= r; r *= qq;
            float y1 = g * c.y; g *= r; r *= qq;
            ull yy0 = pk2(y0, y0), yy1 = pk2(y1, y1);
#pragma unroll
            for (int p = 0; p < NPAIR; p++) {
                ull s1v = mul2(yy0, us2[p]);
                ull s2v = fma2(ar2[p], usq[p], s1v);
                ull ain = fma2(ai2[p], ucq[p], s2v);
                ull s3v = fma2(yy0, uc2[p], yy1);
                ull s4v = fma2(ai2[p], nusq[p], s3v);
                ar2[p]  = fma2(ar2[p], ucq[p], s4v);
                ai2[p]  = ain;
            }
            y0 = g * c.z; g *= r; r *= qq;
            y1 = g * c.w; g *= r; r *= qq;
            yy0 = pk2(y0, y0); yy1 = pk2(y1, y1);
#pragma unroll
            for (int p = 0; p < NPAIR; p++) {
                ull s1v = mul2(yy0, us2[p]);
                ull s2v = fma2(ar2[p], usq[p], s1v);
                ull ain = fma2(ai2[p], ucq[p], s2v);
                ull s3v = fma2(yy0, uc2[p], yy1);
                ull s4v = fma2(ai2[p], nusq[p], s3v);
                ar2[p]  = fma2(ar2[p], ucq[p], s4v);
                ai2[p]  = ain;
            }
        }
#pragma unroll
        for (int p = 0; p < NPAIR; p++) {
            upk2(ar2[p], s_ar[seg][bh][b][2 * p], s_ar[seg][bh][b][2 * p + 1]);
            upk2(ai2[p], s_ai[seg][bh][b][2 * p], s_ai[seg][bh][b][2 * p + 1]);
        }

        // Pass A (zero stores) while other warps may still be in DFT
#pragma unroll
        for (int j = 0; j < 8; j++) {
            int tk = (w << 3) | j;
            int rr2 = tk >> 1, h = tk & 1;
            float bqr = s_bq[rr2];
            float* base = out + ((size_t)(rr2 * NFILT + f) << 10) + (h << 9);
#pragma unroll
            for (int v = 0; v < 4; v++) {
                float nmin = (float)(897 - (h << 9) - (v << 7));
                if (bqr * nmin > DEADX)
                    __stcs((float4*)(base + (v << 7) + (lane << 2)), z4);
            }
        }
        __syncthreads();

        // combine + reduce over 64 batches
        if (tid < 64) {
            int bb = tid;
            float msq = 0.0f;
#pragma unroll
            for (int i = 0; i < NBINS; i++) {
                int k = klo + i;
                int h = i >> 2, ii = i & 3;
                float R = 0.0f, I = 0.0f;
#pragma unroll
                for (int s = 0; s < 4; s++) {
                    float rr2 = s_ar[s][h][bb][ii];
                    float iv  = s_ai[s][h][bb][ii];
                    int mc = (k * (3 - s)) & 3;
                    float r2 = (mc == 0) ? rr2 : (mc == 1) ? -iv : (mc == 2) ? -rr2 : iv;
                    float i2 = (mc == 0) ? iv  : (mc == 1) ?  rr2 : (mc == 2) ? -iv : -rr2;
                    R += r2; I += i2;
                }
                msq = fmaxf(msq, fmaf(R, R, I * I));
            }
#pragma unroll
            for (int o = 16; o; o >>= 1)
                msq = fmaxf(msq, __shfl_xor_sync(0xffffffffu, msq, o));
            if (lane == 0) s_max[tid >> 5] = msq;
        }
        __syncthreads();
    } else {
        // ============== LIGHT PATH: top-2-Q micro-DFT ==============
        if (w == 0) {                              // top-2 Q over 64 batches
            float qA = Q[lane * NFILT + f];
            float qB = Q[(lane + 32) * NFILT + f];
            float v1, v2; int i1, i2;
            if (qA >= qB) { v1 = qA; i1 = lane;      v2 = qB; i2 = lane + 32; }
            else          { v1 = qB; i1 = lane + 32; v2 = qA; i2 = lane; }
#pragma unroll
            for (int o = 16; o; o >>= 1) {
                float u1 = __shfl_xor_sync(0xffffffffu, v1, o);
                int   j1 = __shfl_xor_sync(0xffffffffu, i1, o);
                float u2 = __shfl_xor_sync(0xffffffffu, v2, o);
                int   j2 = __shfl_xor_sync(0xffffffffu, i2, o);
                if (u1 > v1) {
                    if (v1 >= u2) { v2 = v1; i2 = i1; } else { v2 = u2; i2 = j2; }
                    v1 = u1; i1 = j1;
                } else if (u1 > v2) { v2 = u1; i2 = j1; }
            }
            if (lane == 0) { s_top[0] = i1; s_top[1] = i2; }
        }
        // Pass A zero stores (only needs s_bq)
#pragma unroll
        for (int j = 0; j < 8; j++) {
            int tk = (w << 3) | j;
            int rr2 = tk >> 1, h = tk & 1;
            float bqr = s_bq[rr2];
            float* base = out + ((size_t)(rr2 * NFILT + f) << 10) + (h << 9);
#pragma unroll
            for (int v = 0; v < 4; v++) {
                float nmin = (float)(897 - (h << 9) - (v << 7));
                if (bqr * nmin > DEADX)
                    __stcs((float4*)(base + (v << 7) + (lane << 2)), z4);
            }
        }
        __syncthreads();                            // s_top ready

        // warp = (batch-sel wb, bin ki); lane = interleaved chain n = lane+1+32t
        int wb = w >> 3;
        int k  = klo + (w & 7);
        int bsel = s_top[wb];
        float qv  = Q[bsel * NFILT + f];
        float bqL = (fcv / qv) * 1.2533141373155003f / 16000.0f;
        float t2L = bqL * bqL;

        int   ns = lane + 1;
        float x0 = bqL * (float)ns;
        float g  = __expf(-x0 * x0);
        float rr = __expf(-t2L * (float)(64 * ns + 1024));  // env(n+32)/env(n)
        float q32 = __expf(-2048.0f * t2L);

        int m0 = (k * ns) & 511;                   // phase/(pi/256) mod 512
        int ms = (k << 5) & 511;
        float cr, ci, sc, ss;
        __sincosf((float)m0 * PI256, &ci, &cr);    // e^{i*theta_k*ns}
        __sincosf((float)ms * PI256, &ss, &sc);    // e^{i*theta_k*32}

        float R = 0.0f, I = 0.0f;
#pragma unroll 4
        for (int t = 0; t < 16; t++) {
            float y = g * s_carr[lane + (t << 5)];
            R = fmaf(y, cr, R);
            I = fmaf(y, ci, I);
            float ncr = fmaf(cr, sc, -(ci * ss));
            ci = fmaf(ci, sc, cr * ss);
            cr = ncr;
            g *= rr; rr *= q32;
        }
#pragma unroll
        for (int o = 16; o; o >>= 1) {
            R += __shfl_xor_sync(0xffffffffu, R, o);
            I += __shfl_xor_sync(0xffffffffu, I, o);
        }
        if (lane == 0) s_part[w] = fmaf(R, R, I * I);
        __syncthreads();
        if (tid == 0) {
            float m = s_part[0];
#pragma unroll
            for (int i = 1; i < 16; i++) m = fmaxf(m, s_part[i]);
            s_max[0] = m; s_max[1] = m;
        }
        __syncthreads();
    }

    float inv = rsqrtf(fmaxf(s_max[0], s_max[1]));

    // fold inv into carrier
    {
        int t0 = tid << 1;
        float2 cv = *(float2*)(s_carr + t0);
        cv.x *= inv; cv.y *= inv;
        *(float2*)(s_cinv + t0) = cv;
    }
    __syncthreads();

    // ---------------- Pass B: live-block stores ----------------
#pragma unroll
    for (int j = 0; j < 8; j++) {
        int tk = (w << 3) | j;
        int rr2 = tk >> 1, h = tk & 1;
        float bqr = s_bq[rr2];
        float* base = out + ((size_t)(rr2 * NFILT + f) << 10) + (h << 9);
#pragma unroll
        for (int v = 0; v < 4; v++) {
            float nmin = (float)(897 - (h << 9) - (v << 7));
            if (bqr * nmin <= DEADX) {
                int nb = 1024 - (h << 9) - (v << 7);
                int nl = nb - (lane << 2);
                float4 c = *(const float4*)(s_cinv + (nl - 4));
                float nf = (float)nl;
                float x0v = bqr * nf;
                float x1v = bqr * (nf - 1.0f);
                float x2v = bqr * (nf - 2.0f);
                float x3v = bqr * (nf - 3.0f);
                float4 o;
                o.x = __expf(-x0v * x0v) * c.w;
                o.y = __expf(-x1v * x1v) * c.z;
                o.z = __expf(-x2v * x2v) * c.y;
                o.w = __expf(-x3v * x3v) * c.x;
                __stcs((float4*)(base + (v << 7) + (lane << 2)), o);
            }
        }
    }
}

extern "C" void kernel_launch(void* const* d_in, const int* in_sizes, int n_in,
                              void* d_out, int out_size) {
    const float* Q  = (const float*)d_in[0];
    const float* fc = (const float*)d_in[1];
    float* out = (float*)d_out;
    (void)in_sizes; (void)n_in; (void)out_size;

    fused_kernel<<<NFILT, 512>>>(Q, fc, out);
}